// round 1
// baseline (speedup 1.0000x reference)
#include <cuda_runtime.h>

#define A_TOT 82944     // 96*96*9 anchors
#define NCLS  80
#define NBOX  32
#define TPB   256
#define MAXB  16
#define EMB   128
#define IDS   500
#define HW    9216      // 96*96

__device__ float g_cls[MAXB];
__device__ float g_reg[MAXB];
__device__ float g_ce[MAXB];
__device__ float g_valid[MAXB];
__device__ int   g_np[MAXB];

__global__ void zero_kernel() {
    int t = threadIdx.x;
    if (t < MAXB) {
        g_cls[t] = 0.f; g_reg[t] = 0.f; g_ce[t] = 0.f; g_valid[t] = 0.f; g_np[t] = 0;
    }
}

__global__ void __launch_bounds__(TPB) main_kernel(
    const float* __restrict__ cls, const float* __restrict__ reg,
    const float* __restrict__ anchors, const float* __restrict__ boxes,
    const int* __restrict__ labels)
{
    const int b    = blockIdx.y;
    const int base = blockIdx.x * TPB;
    const int tid  = threadIdx.x;

    __shared__ float4 sbox[NBOX];
    __shared__ float  sareab[NBOX];
    __shared__ int    slab[NBOX];
    __shared__ unsigned char sstate[TPB];   // 0 = skip, 1 = neg, 2 = pos
    __shared__ unsigned char slabel[TPB];
    __shared__ float  sred[3];               // reg_sum, npos, cls_sum

    if (tid < NBOX) {
        float4 bx = reinterpret_cast<const float4*>(boxes)[b * NBOX + tid]; // x1,y1,x2,y2
        sbox[tid]   = bx;
        sareab[tid] = (bx.z - bx.x) * (bx.w - bx.y);
        slab[tid]   = labels[b * NBOX + tid];
    }
    if (tid < 3) sred[tid] = 0.f;
    __syncthreads();

    const int a = base + tid;
    const float4 an = reinterpret_cast<const float4*>(anchors)[a];  // y1,x1,y2,x2
    const float aw = an.w - an.y;
    const float ah = an.z - an.x;
    const float area_a = ah * aw;

    float best = -1.f;
    int   barg = 0;
    #pragma unroll 8
    for (int n = 0; n < NBOX; n++) {
        float4 bx = sbox[n];
        float iw = fmaxf(fminf(an.w, bx.z) - fmaxf(an.y, bx.x), 0.f);
        float ih = fmaxf(fminf(an.z, bx.w) - fmaxf(an.x, bx.y), 0.f);
        float inter = iw * ih;
        float ua = fmaxf(area_a + sareab[n] - inter, 1e-8f);
        float iou = inter / ua;
        if (iou > best) { best = iou; barg = n; }   // strict > keeps first max (jnp.argmax)
    }
    const bool pos = (best >= 0.5f);
    sstate[tid] = pos ? 2 : ((best < 0.4f) ? 1 : 0);
    slabel[tid] = (unsigned char)slab[barg];

    float regsum = 0.f;
    float nposf  = pos ? 1.f : 0.f;
    if (pos) {
        float4 gb = sbox[barg];
        float gw = gb.z - gb.x, gh = gb.w - gb.y;
        float gcx = gb.x + 0.5f * gw;
        float gcy = gb.y + 0.5f * gh;
        gw = fmaxf(gw, 1.f);
        gh = fmaxf(gh, 1.f);
        float acx = an.y + 0.5f * aw;
        float acy = an.x + 0.5f * ah;
        float4 r = reinterpret_cast<const float4*>(reg)[(size_t)b * A_TOT + a];
        float t, d;
        t = (gcy - acy) / ah; d = fabsf(t - r.x);
        regsum += (d <= (1.f/9.f)) ? 4.5f * d * d : d - (0.5f/9.f);
        t = (gcx - acx) / aw; d = fabsf(t - r.y);
        regsum += (d <= (1.f/9.f)) ? 4.5f * d * d : d - (0.5f/9.f);
        t = logf(gh / ah);    d = fabsf(t - r.z);
        regsum += (d <= (1.f/9.f)) ? 4.5f * d * d : d - (0.5f/9.f);
        t = logf(gw / aw);    d = fabsf(t - r.w);
        regsum += (d <= (1.f/9.f)) ? 4.5f * d * d : d - (0.5f/9.f);
    }
    #pragma unroll
    for (int o = 16; o; o >>= 1) {
        regsum += __shfl_down_sync(0xffffffffu, regsum, o);
        nposf  += __shfl_down_sync(0xffffffffu, nposf,  o);
    }
    if ((tid & 31) == 0) {
        atomicAdd(&sred[0], regsum);
        atomicAdd(&sred[1], nposf);
    }
    __syncthreads();               // sstate/slabel visible + sred[0..1] complete
    if (tid == 0) {
        atomicAdd(&g_reg[b], sred[0]);
        atomicAdd(&g_np[b], (int)(sred[1] + 0.5f));
    }

    // ---- focal classification loss: stream 256 anchors x 80 classes as float4 ----
    const float4* cp = reinterpret_cast<const float4*>(
        cls + ((size_t)b * A_TOT + base) * NCLS);
    float csum = 0.f;
    const int NV = TPB * NCLS / 4;     // 5120 float4 per block
    #pragma unroll 4
    for (int i = tid; i < NV; i += TPB) {
        int la = i / (NCLS / 4);       // anchor within block
        unsigned char st = sstate[la];
        if (st == 0) continue;         // targets == -1 everywhere for this anchor
        float4 v = cp[i];
        int c0 = (i - la * (NCLS / 4)) * 4;
        int lab = (st == 2) ? (int)slabel[la] : -1;
        float pv[4] = {v.x, v.y, v.z, v.w};
        #pragma unroll
        for (int k = 0; k < 4; k++) {
            float p = fminf(fmaxf(pv[k], 1e-4f), 0.9999f);
            bool one = (c0 + k) == lab;
            float bm = one ? (1.f - p) : p;
            float af = one ? 0.25f : 0.75f;
            csum += af * bm * bm * (-logf(one ? p : 1.f - p));
        }
    }
    #pragma unroll
    for (int o = 16; o; o >>= 1) csum += __shfl_down_sync(0xffffffffu, csum, o);
    if ((tid & 31) == 0) atomicAdd(&sred[2], csum);
    __syncthreads();
    if (tid == 0) atomicAdd(&g_cls[b], sred[2]);
}

__global__ void __launch_bounds__(EMB) reid_kernel(
    const float* __restrict__ emb, const float* __restrict__ boxes,
    const int* __restrict__ reids, const float* __restrict__ Wt,
    const float* __restrict__ bt, const float* __restrict__ escale)
{
    const int bn  = blockIdx.x;
    const int b   = bn >> 5;           // / NBOX
    const int tid = threadIdx.x;       // 128 threads = one channel each

    __shared__ float sfeat[EMB];
    __shared__ float snorm;
    __shared__ float wtmp[4];
    __shared__ float starget;

    float4 bx = reinterpret_cast<const float4*>(boxes)[bn];  // x1,y1,x2,y2
    float cx = floorf((bx.x + bx.z) * 0.125f);
    float cy = floorf((bx.y + bx.w) * 0.125f);
    int ind = (int)(cy * 96.f + cx);

    float f = emb[((size_t)b * EMB + tid) * HW + ind];
    float ss = f * f;
    #pragma unroll
    for (int o = 16; o; o >>= 1) ss += __shfl_down_sync(0xffffffffu, ss, o);
    if (tid == 0) snorm = 0.f;
    __syncthreads();
    if ((tid & 31) == 0) atomicAdd(&snorm, ss);
    __syncthreads();
    float scale = escale[0] / fmaxf(sqrtf(snorm), 1e-12f);
    sfeat[tid] = f * scale;
    __syncthreads();

    // logits for ids {tid, tid+128, tid+256, tid+384}
    bool v3 = (tid + 384) < IDS;
    float lg0 = bt[tid];
    float lg1 = bt[tid + 128];
    float lg2 = bt[tid + 256];
    float lg3 = v3 ? bt[tid + 384] : -1e30f;
    #pragma unroll 8
    for (int ch = 0; ch < EMB; ch++) {
        float fv = sfeat[ch];
        const float* wr = Wt + (size_t)ch * IDS + tid;
        lg0 += fv * wr[0];
        lg1 += fv * wr[128];
        lg2 += fv * wr[256];
        float w3 = v3 ? wr[384] : 0.f;
        lg3 += fv * w3;
    }

    // block max
    float m = fmaxf(fmaxf(lg0, lg1), fmaxf(lg2, lg3));
    #pragma unroll
    for (int o = 16; o; o >>= 1) m = fmaxf(m, __shfl_xor_sync(0xffffffffu, m, o));
    if ((tid & 31) == 0) wtmp[tid >> 5] = m;
    __syncthreads();
    m = fmaxf(fmaxf(wtmp[0], wtmp[1]), fmaxf(wtmp[2], wtmp[3]));
    __syncthreads();

    // block sum of exp
    float e = expf(lg0 - m) + expf(lg1 - m) + expf(lg2 - m)
            + (v3 ? expf(lg3 - m) : 0.f);
    #pragma unroll
    for (int o = 16; o; o >>= 1) e += __shfl_xor_sync(0xffffffffu, e, o);
    if ((tid & 31) == 0) wtmp[tid >> 5] = e;
    __syncthreads();
    float tot = wtmp[0] + wtmp[1] + wtmp[2] + wtmp[3];
    float lse = m + logf(tot);

    int rid = reids[bn];
    int rc  = rid < 0 ? 0 : rid;
    if (tid == (rc & 127)) {
        int j = rc >> 7;
        starget = (j == 0) ? lg0 : (j == 1) ? lg1 : (j == 2) ? lg2 : lg3;
    }
    __syncthreads();
    if (tid == 0) {
        float valid = (rid >= 0) ? 1.f : 0.f;
        atomicAdd(&g_ce[b], (lse - starget) * valid);
        atomicAdd(&g_valid[b], valid);
    }
}

__global__ void final_kernel(float* __restrict__ out, int B) {
    if (threadIdx.x == 0) {
        float cs = 0.f, rs = 0.f, ts = 0.f;
        for (int b = 0; b < B; b++) {
            float np = (float)g_np[b];
            cs += g_cls[b] / fmaxf(np, 1.f);
            rs += g_reg[b] / fmaxf(np * 4.f, 1.f);
            ts += (np > 0.f) ? g_ce[b] / fmaxf(g_valid[b], 1.f) : 0.f;
        }
        float inv = 1.f / (float)B;
        out[0] = cs * inv;
        out[1] = rs * inv * 50.f;
        out[2] = ts * inv;
    }
}

extern "C" void kernel_launch(void* const* d_in, const int* in_sizes, int n_in,
                              void* d_out, int out_size)
{
    const float* cls     = (const float*)d_in[0];   // [B,A,80]
    const float* reg     = (const float*)d_in[1];   // [B,A,4]
    const float* anchors = (const float*)d_in[2];   // [1,A,4]
    const float* emb     = (const float*)d_in[3];   // [B,128,96,96]
    const float* boxes   = (const float*)d_in[4];   // [B,32,4]
    const int*   labels  = (const int*)d_in[5];     // [B,32]
    const int*   reids   = (const int*)d_in[6];     // [B,32]
    const float* Wt      = (const float*)d_in[7];   // [128,500]
    const float* bt      = (const float*)d_in[8];   // [500]
    const float* es      = (const float*)d_in[9];   // scalar

    int B = in_sizes[0] / (A_TOT * NCLS);
    if (B < 1) B = 1;
    if (B > MAXB) B = MAXB;

    zero_kernel<<<1, 32>>>();
    main_kernel<<<dim3(A_TOT / TPB, B), TPB>>>(cls, reg, anchors, boxes, labels);
    reid_kernel<<<B * NBOX, EMB>>>(emb, boxes, reids, Wt, bt, es);
    final_kernel<<<1, 32>>>((float*)d_out, B);
}

// round 2
// speedup vs baseline: 1.6824x; 1.6824x over previous
#include <cuda_runtime.h>

#define A_TOT 82944     // 96*96*9 anchors
#define NCLS  80
#define NBOX  32
#define TPB   256
#define NBLK  (A_TOT / TPB)   // 324
#define MAXB  16
#define EMB   128
#define IDS   500
#define HW    9216      // 96*96

// per-block partials: x=cls_sum, y=reg_sum, z=num_pos
__device__ float4 g_mpart[NBLK * MAXB];
// per-(b,n) reid partials: x=ce, y=valid
__device__ float2 g_rpart[NBOX * MAXB];

__global__ void __launch_bounds__(TPB) main_kernel(
    const float* __restrict__ cls, const float* __restrict__ reg,
    const float* __restrict__ anchors, const float* __restrict__ boxes,
    const int* __restrict__ labels)
{
    const int b    = blockIdx.y;
    const int base = blockIdx.x * TPB;
    const int tid  = threadIdx.x;

    __shared__ float4 sbox[NBOX];
    __shared__ float  sareab[NBOX];
    __shared__ int    slab[NBOX];
    __shared__ float  sweight[TPB];     // 0.0 (ignore) or 0.75 (counted)
    __shared__ float  sred[3];          // cls, reg, npos

    if (tid < NBOX) {
        float4 bx = reinterpret_cast<const float4*>(boxes)[b * NBOX + tid]; // x1,y1,x2,y2
        sbox[tid]   = bx;
        sareab[tid] = (bx.z - bx.x) * (bx.w - bx.y);
        slab[tid]   = labels[b * NBOX + tid];
    }
    if (tid < 3) sred[tid] = 0.f;
    __syncthreads();

    const int a = base + tid;
    const float4 an = reinterpret_cast<const float4*>(anchors)[a];  // y1,x1,y2,x2
    const float aw = an.w - an.y;
    const float ah = an.z - an.x;
    const float area_a = ah * aw;

    float best = -1.f;
    int   barg = 0;
    #pragma unroll 8
    for (int n = 0; n < NBOX; n++) {
        float4 bx = sbox[n];
        float iw = fmaxf(fminf(an.w, bx.z) - fmaxf(an.y, bx.x), 0.f);
        float ih = fmaxf(fminf(an.z, bx.w) - fmaxf(an.x, bx.y), 0.f);
        float inter = iw * ih;
        float ua = fmaxf(area_a + sareab[n] - inter, 1e-8f);
        float iou = inter / ua;
        if (iou > best) { best = iou; barg = n; }   // strict > == first argmax
    }
    const bool pos    = (best >= 0.5f);
    const bool ignore = (best >= 0.4f) && !pos;
    sweight[tid] = ignore ? 0.f : 0.75f;

    float regsum = 0.f;
    float nposf  = pos ? 1.f : 0.f;
    float csum   = 0.f;
    if (pos) {
        float4 gb = sbox[barg];
        float gw = gb.z - gb.x, gh = gb.w - gb.y;
        float gcx = gb.x + 0.5f * gw;
        float gcy = gb.y + 0.5f * gh;
        gw = fmaxf(gw, 1.f);
        gh = fmaxf(gh, 1.f);
        float acx = an.y + 0.5f * aw;
        float acy = an.x + 0.5f * ah;
        float4 r = reinterpret_cast<const float4*>(reg)[(size_t)b * A_TOT + a];
        float t, d;
        t = (gcy - acy) / ah; d = fabsf(t - r.x);
        regsum += (d <= (1.f/9.f)) ? 4.5f * d * d : d - (0.5f/9.f);
        t = (gcx - acx) / aw; d = fabsf(t - r.y);
        regsum += (d <= (1.f/9.f)) ? 4.5f * d * d : d - (0.5f/9.f);
        t = logf(gh / ah);    d = fabsf(t - r.z);
        regsum += (d <= (1.f/9.f)) ? 4.5f * d * d : d - (0.5f/9.f);
        t = logf(gw / aw);    d = fabsf(t - r.w);
        regsum += (d <= (1.f/9.f)) ? 4.5f * d * d : d - (0.5f/9.f);

        // sparse focal correction for the single target class of this anchor:
        // add 0.25(1-p)^2(-log p) and remove the uniform 0.75 p^2 (-log(1-p))
        int lab = slab[barg];
        float pv = cls[((size_t)b * A_TOT + a) * NCLS + lab];
        float p  = fminf(fmaxf(pv, 1e-4f), 0.9999f);
        float omp = 1.f - p;
        float lt = __logf(p);
        float lo = __logf(omp);
        csum = -0.25f * omp * omp * lt + 0.75f * p * p * lo;
    }
    __syncthreads();   // sweight visible

    // ---- uniform focal term: 0.75 * p^2 * (-log(1-p)) weighted per anchor ----
    const float4* cp = reinterpret_cast<const float4*>(
        cls + ((size_t)b * A_TOT + base) * NCLS);
    #pragma unroll 10
    for (int j = 0; j < NCLS / 4; j++) {     // 20 float4s per thread, stride TPB
        int i = tid + j * TPB;
        int la = i / (NCLS / 4);
        float w = sweight[la];
        float4 v = __ldcs(cp + i);
        float s4;
        {
            float p = fminf(fmaxf(v.x, 1e-4f), 0.9999f);
            s4 = p * p * __logf(1.f - p);
        }
        {
            float p = fminf(fmaxf(v.y, 1e-4f), 0.9999f);
            s4 = fmaf(p * p, __logf(1.f - p), s4);
        }
        {
            float p = fminf(fmaxf(v.z, 1e-4f), 0.9999f);
            s4 = fmaf(p * p, __logf(1.f - p), s4);
        }
        {
            float p = fminf(fmaxf(v.w, 1e-4f), 0.9999f);
            s4 = fmaf(p * p, __logf(1.f - p), s4);
        }
        csum = fmaf(s4, -w, csum);           // w = 0 or 0.75, log(1-p) < 0
    }

    #pragma unroll
    for (int o = 16; o; o >>= 1) {
        csum   += __shfl_down_sync(0xffffffffu, csum,   o);
        regsum += __shfl_down_sync(0xffffffffu, regsum, o);
        nposf  += __shfl_down_sync(0xffffffffu, nposf,  o);
    }
    if ((tid & 31) == 0) {
        atomicAdd(&sred[0], csum);
        atomicAdd(&sred[1], regsum);
        atomicAdd(&sred[2], nposf);
    }
    __syncthreads();
    if (tid == 0)
        g_mpart[b * NBLK + blockIdx.x] = make_float4(sred[0], sred[1], sred[2], 0.f);
}

__global__ void __launch_bounds__(EMB) reid_kernel(
    const float* __restrict__ emb, const float* __restrict__ boxes,
    const int* __restrict__ reids, const float* __restrict__ Wt,
    const float* __restrict__ bt, const float* __restrict__ escale)
{
    const int bn  = blockIdx.x;
    const int b   = bn >> 5;           // / NBOX
    const int tid = threadIdx.x;

    __shared__ float sfeat[EMB];
    __shared__ float snorm;
    __shared__ float wtmp[4];
    __shared__ float starget;

    float4 bx = reinterpret_cast<const float4*>(boxes)[bn];  // x1,y1,x2,y2
    float cx = floorf((bx.x + bx.z) * 0.125f);
    float cy = floorf((bx.y + bx.w) * 0.125f);
    int ind = (int)(cy * 96.f + cx);

    float f = emb[((size_t)b * EMB + tid) * HW + ind];
    float ss = f * f;
    #pragma unroll
    for (int o = 16; o; o >>= 1) ss += __shfl_down_sync(0xffffffffu, ss, o);
    if (tid == 0) snorm = 0.f;
    __syncthreads();
    if ((tid & 31) == 0) atomicAdd(&snorm, ss);
    __syncthreads();
    float scale = escale[0] / fmaxf(sqrtf(snorm), 1e-12f);
    sfeat[tid] = f * scale;
    __syncthreads();

    bool v3 = (tid + 384) < IDS;
    float lg0 = bt[tid];
    float lg1 = bt[tid + 128];
    float lg2 = bt[tid + 256];
    float lg3 = v3 ? bt[tid + 384] : -1e30f;
    #pragma unroll 8
    for (int ch = 0; ch < EMB; ch++) {
        float fv = sfeat[ch];
        const float* wr = Wt + (size_t)ch * IDS + tid;
        lg0 = fmaf(fv, wr[0],   lg0);
        lg1 = fmaf(fv, wr[128], lg1);
        lg2 = fmaf(fv, wr[256], lg2);
        float w3 = v3 ? wr[384] : 0.f;
        lg3 = fmaf(fv, w3, lg3);
    }

    float m = fmaxf(fmaxf(lg0, lg1), fmaxf(lg2, lg3));
    #pragma unroll
    for (int o = 16; o; o >>= 1) m = fmaxf(m, __shfl_xor_sync(0xffffffffu, m, o));
    if ((tid & 31) == 0) wtmp[tid >> 5] = m;
    __syncthreads();
    m = fmaxf(fmaxf(wtmp[0], wtmp[1]), fmaxf(wtmp[2], wtmp[3]));
    __syncthreads();

    float e = __expf(lg0 - m) + __expf(lg1 - m) + __expf(lg2 - m)
            + (v3 ? __expf(lg3 - m) : 0.f);
    #pragma unroll
    for (int o = 16; o; o >>= 1) e += __shfl_xor_sync(0xffffffffu, e, o);
    if ((tid & 31) == 0) wtmp[tid >> 5] = e;
    __syncthreads();
    float tot = wtmp[0] + wtmp[1] + wtmp[2] + wtmp[3];
    float lse = m + __logf(tot);

    int rid = reids[bn];
    int rc  = rid < 0 ? 0 : rid;
    if (tid == (rc & 127)) {
        int j = rc >> 7;
        starget = (j == 0) ? lg0 : (j == 1) ? lg1 : (j == 2) ? lg2 : lg3;
    }
    __syncthreads();
    if (tid == 0) {
        float valid = (rid >= 0) ? 1.f : 0.f;
        g_rpart[bn] = make_float2((lse - starget) * valid, valid);
    }
}

__global__ void __launch_bounds__(512) final_kernel(float* __restrict__ out, int B) {
    __shared__ float scls[MAXB], sreg[MAXB], strk[MAXB];
    const int w    = threadIdx.x >> 5;
    const int lane = threadIdx.x & 31;

    if (w < B) {
        float c = 0.f, r = 0.f, np = 0.f;
        for (int i = lane; i < NBLK; i += 32) {
            float4 p = g_mpart[w * NBLK + i];
            c += p.x; r += p.y; np += p.z;
        }
        float2 rp = g_rpart[w * NBOX + lane];   // NBOX == 32, one per lane
        float ce = rp.x, va = rp.y;
        #pragma unroll
        for (int o = 16; o; o >>= 1) {
            c  += __shfl_down_sync(0xffffffffu, c,  o);
            r  += __shfl_down_sync(0xffffffffu, r,  o);
            np += __shfl_down_sync(0xffffffffu, np, o);
            ce += __shfl_down_sync(0xffffffffu, ce, o);
            va += __shfl_down_sync(0xffffffffu, va, o);
        }
        if (lane == 0) {
            scls[w] = c / fmaxf(np, 1.f);
            sreg[w] = r / fmaxf(np * 4.f, 1.f);
            strk[w] = (np > 0.f) ? ce / fmaxf(va, 1.f) : 0.f;
        }
    }
    __syncthreads();
    if (threadIdx.x == 0) {
        float cs = 0.f, rs = 0.f, ts = 0.f;
        for (int b = 0; b < B; b++) { cs += scls[b]; rs += sreg[b]; ts += strk[b]; }
        float inv = 1.f / (float)B;
        out[0] = cs * inv;
        out[1] = rs * inv * 50.f;
        out[2] = ts * inv;
    }
}

extern "C" void kernel_launch(void* const* d_in, const int* in_sizes, int n_in,
                              void* d_out, int out_size)
{
    const float* cls     = (const float*)d_in[0];   // [B,A,80]
    const float* reg     = (const float*)d_in[1];   // [B,A,4]
    const float* anchors = (const float*)d_in[2];   // [1,A,4]
    const float* emb     = (const float*)d_in[3];   // [B,128,96,96]
    const float* boxes   = (const float*)d_in[4];   // [B,32,4]
    const int*   labels  = (const int*)d_in[5];     // [B,32]
    const int*   reids   = (const int*)d_in[6];     // [B,32]
    const float* Wt      = (const float*)d_in[7];   // [128,500]
    const float* bt      = (const float*)d_in[8];   // [500]
    const float* es      = (const float*)d_in[9];   // scalar

    int B = in_sizes[0] / (A_TOT * NCLS);
    if (B < 1) B = 1;
    if (B > MAXB) B = MAXB;

    main_kernel<<<dim3(NBLK, B), TPB>>>(cls, reg, anchors, boxes, labels);
    reid_kernel<<<B * NBOX, EMB>>>(emb, boxes, reids, Wt, bt, es);
    final_kernel<<<1, 512>>>((float*)d_out, B);
}

// round 3
// speedup vs baseline: 3.1433x; 1.8683x over previous
#include <cuda_runtime.h>

#define A_TOT 82944     // 96*96*9 anchors
#define NCLS  80
#define NBOX  32
#define TPB   256
#define NBLK  (A_TOT / TPB)   // 324
#define RBLK  (NBOX / 2)      // 16 reid blocks per image (2 boxes each)
#define MAXB  16
#define EMB   128
#define IDS   500
#define HW    9216            // 96*96

// -0.75 * ln(2): converts log2-domain accumulator to the 0.75-weighted ln term
#define NEG_W_LN2 0.5198603854199589f

__device__ float4   g_mpart[NBLK * MAXB];   // x=cls, y=reg, z=npos
__device__ float2   g_rpart[NBOX * MAXB];   // x=ce, y=valid
__device__ unsigned g_ticket = 0;

__global__ void __launch_bounds__(TPB, 5) fused_kernel(
    const float* __restrict__ cls, const float* __restrict__ reg,
    const float* __restrict__ anchors, const float* __restrict__ boxes,
    const int* __restrict__ labels, const float* __restrict__ emb,
    const int* __restrict__ reids, const float* __restrict__ Wt,
    const float* __restrict__ bt, const float* __restrict__ escale,
    float* __restrict__ out, int B)
{
    const int b   = blockIdx.y;
    const int tid = threadIdx.x;

    __shared__ float4 sbox[NBOX];
    __shared__ float  sareab[NBOX];
    __shared__ int    slab[NBOX];
    __shared__ float  sred[4];                 // cls, reg, npos (block partials)
    __shared__ float  sfeat[2][EMB];
    __shared__ float  snorm[2];
    __shared__ float  wtmp[2][4];
    __shared__ float  starg[2];
    __shared__ int    sdone;
    __shared__ float  sacc[3];

    if (blockIdx.x < NBLK) {
        // =========================== main: IoU + focal + reg ===========================
        if (tid < NBOX) {
            float4 bx = reinterpret_cast<const float4*>(boxes)[b * NBOX + tid]; // x1,y1,x2,y2
            sbox[tid]   = bx;
            sareab[tid] = (bx.z - bx.x) * (bx.w - bx.y);
            slab[tid]   = labels[b * NBOX + tid];
        }
        if (tid < 4) sred[tid] = 0.f;
        __syncthreads();

        const int a = blockIdx.x * TPB + tid;
        const float4 an = reinterpret_cast<const float4*>(anchors)[a];  // y1,x1,y2,x2
        const float aw = an.w - an.y;
        const float ah = an.z - an.x;
        const float area_a = ah * aw;

        // division-free argmax over IoU: keep (inter_b, ua_b)
        float ib = -1.f, ub = 1.f;
        int   barg = 0;
        #pragma unroll
        for (int n = 0; n < NBOX; n++) {
            float4 bx = sbox[n];
            float iw = fmaxf(fminf(an.w, bx.z) - fmaxf(an.y, bx.x), 0.f);
            float ih = fmaxf(fminf(an.z, bx.w) - fmaxf(an.x, bx.y), 0.f);
            float inter = iw * ih;
            float ua = fmaxf(area_a + sareab[n] - inter, 1e-8f);
            if (inter * ub > ib * ua) { ib = inter; ub = ua; barg = n; }  // strict > == first argmax
        }
        const bool pos = (ib >= 0.5f * ub);
        const bool ign = !pos && (ib >= 0.4f * ub);

        // ---- uniform focal stream: sum p^2 * log2(1-p) over ALL 256 anchors x 80 classes ----
        const float4* cp = reinterpret_cast<const float4*>(cls)
                         + ((size_t)b * A_TOT + (size_t)blockIdx.x * TPB) * (NCLS / 4);
        float a0 = 0.f, a1 = 0.f;
        #pragma unroll
        for (int j = 0; j < NCLS / 4; j++) {
            float4 v = __ldcs(cp + j * TPB + tid);
            float p0 = fminf(v.x, 0.9999f);
            float p1 = fminf(v.y, 0.9999f);
            float p2 = fminf(v.z, 0.9999f);
            float p3 = fminf(v.w, 0.9999f);
            a0 = fmaf(p0 * p0, __log2f(1.f - p0), a0);
            a1 = fmaf(p1 * p1, __log2f(1.f - p1), a1);
            a0 = fmaf(p2 * p2, __log2f(1.f - p2), a0);
            a1 = fmaf(p3 * p3, __log2f(1.f - p3), a1);
        }
        float csum = a0 + a1;          // log2 domain, weight applied at the end

        // ---- sparse corrections ----
        float corr = 0.f, regsum = 0.f;
        float nposf = pos ? 1.f : 0.f;
        if (pos) {
            float4 gb = sbox[barg];
            float gw = gb.z - gb.x, gh = gb.w - gb.y;
            float gcx = gb.x + 0.5f * gw;
            float gcy = gb.y + 0.5f * gh;
            gw = fmaxf(gw, 1.f);
            gh = fmaxf(gh, 1.f);
            float acx = an.y + 0.5f * aw;
            float acy = an.x + 0.5f * ah;
            float4 r = reinterpret_cast<const float4*>(reg)[(size_t)b * A_TOT + a];
            float t, d;
            t = (gcy - acy) / ah; d = fabsf(t - r.x);
            regsum += (d <= (1.f/9.f)) ? 4.5f * d * d : d - (0.5f/9.f);
            t = (gcx - acx) / aw; d = fabsf(t - r.y);
            regsum += (d <= (1.f/9.f)) ? 4.5f * d * d : d - (0.5f/9.f);
            t = __logf(gh / ah);  d = fabsf(t - r.z);
            regsum += (d <= (1.f/9.f)) ? 4.5f * d * d : d - (0.5f/9.f);
            t = __logf(gw / aw);  d = fabsf(t - r.w);
            regsum += (d <= (1.f/9.f)) ? 4.5f * d * d : d - (0.5f/9.f);

            // replace the uniform negative term with the positive focal term for the target class
            int lab = slab[barg];
            float pv = __ldg(cls + ((size_t)b * A_TOT + a) * NCLS + lab);
            float p  = fminf(fmaxf(pv, 1e-4f), 0.9999f);
            float omp = 1.f - p;
            corr = -0.25f * omp * omp * __logf(p) + 0.75f * p * p * __logf(omp);
        }
        if (ign) {
            // this anchor is ignored entirely: subtract its full row (same formula -> cancels)
            const float4* rp = reinterpret_cast<const float4*>(cls)
                             + ((size_t)b * A_TOT + a) * (NCLS / 4);
            float r0 = 0.f, r1 = 0.f;
            #pragma unroll
            for (int j = 0; j < NCLS / 4; j++) {
                float4 v = __ldg(rp + j);
                float p0 = fminf(v.x, 0.9999f);
                float p1 = fminf(v.y, 0.9999f);
                float p2 = fminf(v.z, 0.9999f);
                float p3 = fminf(v.w, 0.9999f);
                r0 = fmaf(p0 * p0, __log2f(1.f - p0), r0);
                r1 = fmaf(p1 * p1, __log2f(1.f - p1), r1);
                r0 = fmaf(p2 * p2, __log2f(1.f - p2), r0);
                r1 = fmaf(p3 * p3, __log2f(1.f - p3), r1);
            }
            csum -= (r0 + r1);
        }

        #pragma unroll
        for (int o = 16; o; o >>= 1) {
            csum   += __shfl_down_sync(0xffffffffu, csum,   o);
            corr   += __shfl_down_sync(0xffffffffu, corr,   o);
            regsum += __shfl_down_sync(0xffffffffu, regsum, o);
            nposf  += __shfl_down_sync(0xffffffffu, nposf,  o);
        }
        if ((tid & 31) == 0) {
            atomicAdd(&sred[0], corr - NEG_W_LN2 * csum);
            atomicAdd(&sred[1], regsum);
            atomicAdd(&sred[2], nposf);
        }
        __syncthreads();
        if (tid == 0)
            g_mpart[b * NBLK + blockIdx.x] = make_float4(sred[0], sred[1], sred[2], 0.f);
    } else {
        // =========================== reid: 2 boxes per block ===========================
        const int grp = tid >> 7;          // 0 or 1 (warp-aligned groups)
        const int t   = tid & 127;
        const int bnl = (blockIdx.x - NBLK) * 2 + grp;   // 0..31
        const int bn  = b * NBOX + bnl;

        float4 bx = reinterpret_cast<const float4*>(boxes)[bn];  // x1,y1,x2,y2
        float cx = floorf((bx.x + bx.z) * 0.125f);
        float cy = floorf((bx.y + bx.w) * 0.125f);
        int ind = (int)(cy * 96.f + cx);

        float f = emb[((size_t)b * EMB + t) * HW + ind];
        float ss = f * f;
        #pragma unroll
        for (int o = 16; o; o >>= 1) ss += __shfl_down_sync(0xffffffffu, ss, o);
        if (t == 0) snorm[grp] = 0.f;
        __syncthreads();
        if ((t & 31) == 0) atomicAdd(&snorm[grp], ss);
        __syncthreads();
        float scale = escale[0] / fmaxf(sqrtf(snorm[grp]), 1e-12f);
        sfeat[grp][t] = f * scale;
        __syncthreads();

        bool v3 = (t + 384) < IDS;
        float lg0 = bt[t];
        float lg1 = bt[t + 128];
        float lg2 = bt[t + 256];
        float lg3 = v3 ? bt[t + 384] : -1e30f;
        #pragma unroll 8
        for (int ch = 0; ch < EMB; ch++) {
            float fv = sfeat[grp][ch];
            const float* wr = Wt + (size_t)ch * IDS + t;
            lg0 = fmaf(fv, wr[0],   lg0);
            lg1 = fmaf(fv, wr[128], lg1);
            lg2 = fmaf(fv, wr[256], lg2);
            float w3 = v3 ? wr[384] : 0.f;
            lg3 = fmaf(fv, w3, lg3);
        }

        float m = fmaxf(fmaxf(lg0, lg1), fmaxf(lg2, lg3));
        #pragma unroll
        for (int o = 16; o; o >>= 1) m = fmaxf(m, __shfl_xor_sync(0xffffffffu, m, o));
        if ((t & 31) == 0) wtmp[grp][t >> 5] = m;
        __syncthreads();
        m = fmaxf(fmaxf(wtmp[grp][0], wtmp[grp][1]), fmaxf(wtmp[grp][2], wtmp[grp][3]));
        __syncthreads();

        float e = __expf(lg0 - m) + __expf(lg1 - m) + __expf(lg2 - m)
                + (v3 ? __expf(lg3 - m) : 0.f);
        #pragma unroll
        for (int o = 16; o; o >>= 1) e += __shfl_xor_sync(0xffffffffu, e, o);
        if ((t & 31) == 0) wtmp[grp][t >> 5] = e;
        __syncthreads();
        float tot = wtmp[grp][0] + wtmp[grp][1] + wtmp[grp][2] + wtmp[grp][3];
        float lse = m + __logf(tot);

        int rid = reids[bn];
        int rc  = rid < 0 ? 0 : rid;
        if (t == (rc & 127)) {
            int j = rc >> 7;
            starg[grp] = (j == 0) ? lg0 : (j == 1) ? lg1 : (j == 2) ? lg2 : lg3;
        }
        __syncthreads();
        if (t == 0) {
            float valid = (rid >= 0) ? 1.f : 0.f;
            g_rpart[bn] = make_float2((lse - starg[grp]) * valid, valid);
        }
    }

    // =========================== grid-wide completion ticket ===========================
    if (tid == 0) {
        __threadfence();
        unsigned total = gridDim.x * gridDim.y;
        unsigned tk = atomicAdd(&g_ticket, 1u);
        sdone = (tk == total - 1u) ? 1 : 0;
    }
    __syncthreads();
    if (!sdone) return;

    // =========================== final reduction (last block only) =====================
    if (tid < 3) sacc[tid] = 0.f;
    __syncthreads();
    const int w = tid >> 5, lane = tid & 31;
    for (int img = w; img < B; img += 8) {
        float c = 0.f, r = 0.f, np = 0.f;
        for (int i = lane; i < NBLK; i += 32) {
            float4 p = __ldcg(&g_mpart[img * NBLK + i]);
            c += p.x; r += p.y; np += p.z;
        }
        float2 rp = __ldcg(&g_rpart[img * NBOX + lane]);   // NBOX == 32
        float ce = rp.x, va = rp.y;
        #pragma unroll
        for (int o = 16; o; o >>= 1) {
            c  += __shfl_down_sync(0xffffffffu, c,  o);
            r  += __shfl_down_sync(0xffffffffu, r,  o);
            np += __shfl_down_sync(0xffffffffu, np, o);
            ce += __shfl_down_sync(0xffffffffu, ce, o);
            va += __shfl_down_sync(0xffffffffu, va, o);
        }
        if (lane == 0) {
            atomicAdd(&sacc[0], c / fmaxf(np, 1.f));
            atomicAdd(&sacc[1], r / fmaxf(np * 4.f, 1.f));
            atomicAdd(&sacc[2], (np > 0.f) ? ce / fmaxf(va, 1.f) : 0.f);
        }
    }
    __syncthreads();
    if (tid == 0) {
        float inv = 1.f / (float)B;
        out[0] = sacc[0] * inv;
        out[1] = sacc[1] * inv * 50.f;
        out[2] = sacc[2] * inv;
        g_ticket = 0;               // reset for next replay -> deterministic
    }
}

extern "C" void kernel_launch(void* const* d_in, const int* in_sizes, int n_in,
                              void* d_out, int out_size)
{
    const float* cls     = (const float*)d_in[0];   // [B,A,80]
    const float* reg     = (const float*)d_in[1];   // [B,A,4]
    const float* anchors = (const float*)d_in[2];   // [1,A,4]
    const float* emb     = (const float*)d_in[3];   // [B,128,96,96]
    const float* boxes   = (const float*)d_in[4];   // [B,32,4]
    const int*   labels  = (const int*)d_in[5];     // [B,32]
    const int*   reids   = (const int*)d_in[6];     // [B,32]
    const float* Wt      = (const float*)d_in[7];   // [128,500]
    const float* bt      = (const float*)d_in[8];   // [500]
    const float* es      = (const float*)d_in[9];   // scalar

    int B = in_sizes[0] / (A_TOT * NCLS);
    if (B < 1) B = 1;
    if (B > MAXB) B = MAXB;

    fused_kernel<<<dim3(NBLK + RBLK, B), TPB>>>(
        cls, reg, anchors, boxes, labels, emb, reids, Wt, bt, es,
        (float*)d_out, B);
}

// round 4
// speedup vs baseline: 3.3528x; 1.0667x over previous
#include <cuda_runtime.h>

#define A_TOT 82944     // 96*96*9 anchors
#define NCLS  80
#define NBOX  32
#define TPB   256
#define NBLK  (A_TOT / TPB)   // 324
#define RBLK  (NBOX / 2)      // 16 reid blocks per image (2 boxes each)
#define MAXB  16
#define EMB   128
#define IDS   500
#define HW    9216            // 96*96

// -0.75 * ln(2): converts log2-domain accumulator to the 0.75-weighted ln term
#define NEG_W_LN2 0.5198603854199589f

__device__ float4   g_mpart[NBLK * MAXB];   // x=cls, y=reg, z=npos
__device__ float2   g_rpart[NBOX * MAXB];   // x=ce, y=valid
__device__ unsigned g_ticket = 0;

__device__ __forceinline__ void foc4(const float4 v, float& a0, float& a1) {
    float p0 = fminf(v.x, 0.9999f);
    float p1 = fminf(v.y, 0.9999f);
    float p2 = fminf(v.z, 0.9999f);
    float p3 = fminf(v.w, 0.9999f);
    a0 = fmaf(p0 * p0, __log2f(1.f - p0), a0);
    a1 = fmaf(p1 * p1, __log2f(1.f - p1), a1);
    a0 = fmaf(p2 * p2, __log2f(1.f - p2), a0);
    a1 = fmaf(p3 * p3, __log2f(1.f - p3), a1);
}

__global__ void __launch_bounds__(TPB, 4) fused_kernel(
    const float* __restrict__ cls, const float* __restrict__ reg,
    const float* __restrict__ anchors, const float* __restrict__ boxes,
    const int* __restrict__ labels, const float* __restrict__ emb,
    const int* __restrict__ reids, const float* __restrict__ Wt,
    const float* __restrict__ bt, const float* __restrict__ escale,
    float* __restrict__ out, int B)
{
    const int b   = blockIdx.y;
    const int tid = threadIdx.x;

    __shared__ float4 sbox[NBOX];
    __shared__ float  sareab[NBOX];
    __shared__ int    slab[NBOX];
    __shared__ float  sred[4];
    __shared__ float  sfeat[2][EMB];
    __shared__ float  snorm[2];
    __shared__ float  wtmp[2][4];
    __shared__ float  starg[2];
    __shared__ int    sdone;
    __shared__ float  sacc[3];

    if (blockIdx.x >= RBLK) {
        // =========================== main: IoU + focal + reg ===========================
        const int mblk = blockIdx.x - RBLK;
        const int a    = mblk * TPB + tid;

        // kick off the stream immediately: 4 float4 loads in flight before any setup
        const float4* cp = reinterpret_cast<const float4*>(cls)
                         + ((size_t)b * A_TOT + (size_t)mblk * TPB) * (NCLS / 4);
        float4 v0 = __ldcs(cp + 0 * TPB + tid);
        float4 v1 = __ldcs(cp + 1 * TPB + tid);
        float4 v2 = __ldcs(cp + 2 * TPB + tid);
        float4 v3 = __ldcs(cp + 3 * TPB + tid);

        if (tid < NBOX) {
            float4 bx = reinterpret_cast<const float4*>(boxes)[b * NBOX + tid]; // x1,y1,x2,y2
            sbox[tid]   = bx;
            sareab[tid] = (bx.z - bx.x) * (bx.w - bx.y);
            slab[tid]   = labels[b * NBOX + tid];
        }
        if (tid < 4) sred[tid] = 0.f;
        __syncthreads();

        const float4 an = reinterpret_cast<const float4*>(anchors)[a];  // y1,x1,y2,x2
        const float aw = an.w - an.y;
        const float ah = an.z - an.x;
        const float area_a = ah * aw;

        // division-free argmax over IoU (strict > == first argmax)
        float ib = -1.f, ub = 1.f;
        int   barg = 0;
        #pragma unroll
        for (int n = 0; n < NBOX; n++) {
            float4 bx = sbox[n];
            float iw = fmaxf(fminf(an.w, bx.z) - fmaxf(an.y, bx.x), 0.f);
            float ih = fmaxf(fminf(an.z, bx.w) - fmaxf(an.x, bx.y), 0.f);
            float inter = iw * ih;
            float ua = fmaxf(area_a + sareab[n] - inter, 1e-8f);
            if (inter * ub > ib * ua) { ib = inter; ub = ua; barg = n; }
        }
        const bool pos = (ib >= 0.5f * ub);
        const bool ign = !pos && (ib >= 0.4f * ub);

        // ---- uniform focal stream, software-pipelined in groups of 4 float4 ----
        float a0 = 0.f, a1 = 0.f;
        #pragma unroll
        for (int g = 0; g < 5; g++) {
            float4 w0, w1, w2, w3;
            if (g < 4) {
                w0 = __ldcs(cp + ((g + 1) * 4 + 0) * TPB + tid);
                w1 = __ldcs(cp + ((g + 1) * 4 + 1) * TPB + tid);
                w2 = __ldcs(cp + ((g + 1) * 4 + 2) * TPB + tid);
                w3 = __ldcs(cp + ((g + 1) * 4 + 3) * TPB + tid);
            }
            foc4(v0, a0, a1);
            foc4(v1, a0, a1);
            foc4(v2, a0, a1);
            foc4(v3, a0, a1);
            v0 = w0; v1 = w1; v2 = w2; v3 = w3;
        }
        float csum = a0 + a1;          // log2 domain

        // ---- sparse corrections ----
        float corr = 0.f, regsum = 0.f;
        float nposf = pos ? 1.f : 0.f;
        if (pos) {
            float4 gb = sbox[barg];
            float gw = gb.z - gb.x, gh = gb.w - gb.y;
            float gcx = gb.x + 0.5f * gw;
            float gcy = gb.y + 0.5f * gh;
            gw = fmaxf(gw, 1.f);
            gh = fmaxf(gh, 1.f);
            float acx = an.y + 0.5f * aw;
            float acy = an.x + 0.5f * ah;
            float4 r = reinterpret_cast<const float4*>(reg)[(size_t)b * A_TOT + a];
            float t, d;
            t = (gcy - acy) / ah; d = fabsf(t - r.x);
            regsum += (d <= (1.f/9.f)) ? 4.5f * d * d : d - (0.5f/9.f);
            t = (gcx - acx) / aw; d = fabsf(t - r.y);
            regsum += (d <= (1.f/9.f)) ? 4.5f * d * d : d - (0.5f/9.f);
            t = __logf(gh / ah);  d = fabsf(t - r.z);
            regsum += (d <= (1.f/9.f)) ? 4.5f * d * d : d - (0.5f/9.f);
            t = __logf(gw / aw);  d = fabsf(t - r.w);
            regsum += (d <= (1.f/9.f)) ? 4.5f * d * d : d - (0.5f/9.f);

            int lab = slab[barg];
            float pv = __ldg(cls + ((size_t)b * A_TOT + a) * NCLS + lab);
            float p  = fminf(fmaxf(pv, 1e-4f), 0.9999f);
            float omp = 1.f - p;
            corr = -0.25f * omp * omp * __logf(p) + 0.75f * p * p * __logf(omp);
        }
        if (ign) {
            // anchor fully ignored: subtract its row with the identical formula
            const float4* rp = reinterpret_cast<const float4*>(cls)
                             + ((size_t)b * A_TOT + a) * (NCLS / 4);
            float r0 = 0.f, r1 = 0.f;
            #pragma unroll
            for (int j = 0; j < NCLS / 4; j++) {
                float4 v = __ldg(rp + j);
                foc4(v, r0, r1);
            }
            csum -= (r0 + r1);
        }

        #pragma unroll
        for (int o = 16; o; o >>= 1) {
            csum   += __shfl_down_sync(0xffffffffu, csum,   o);
            corr   += __shfl_down_sync(0xffffffffu, corr,   o);
            regsum += __shfl_down_sync(0xffffffffu, regsum, o);
            nposf  += __shfl_down_sync(0xffffffffu, nposf,  o);
        }
        if ((tid & 31) == 0) {
            atomicAdd(&sred[0], corr - NEG_W_LN2 * csum);
            atomicAdd(&sred[1], regsum);
            atomicAdd(&sred[2], nposf);
        }
        __syncthreads();
        if (tid == 0)
            g_mpart[b * NBLK + mblk] = make_float4(sred[0], sred[1], sred[2], 0.f);
    } else {
        // =========================== reid: 2 boxes per block ===========================
        const int grp = tid >> 7;
        const int t   = tid & 127;
        const int bnl = blockIdx.x * 2 + grp;            // 0..31
        const int bn  = b * NBOX + bnl;

        float4 bx = reinterpret_cast<const float4*>(boxes)[bn];  // x1,y1,x2,y2
        float cx = floorf((bx.x + bx.z) * 0.125f);
        float cy = floorf((bx.y + bx.w) * 0.125f);
        int ind = (int)(cy * 96.f + cx);

        float f = emb[((size_t)b * EMB + t) * HW + ind];
        float ss = f * f;
        #pragma unroll
        for (int o = 16; o; o >>= 1) ss += __shfl_down_sync(0xffffffffu, ss, o);
        if (t == 0) snorm[grp] = 0.f;
        __syncthreads();
        if ((t & 31) == 0) atomicAdd(&snorm[grp], ss);
        __syncthreads();
        float scale = escale[0] / fmaxf(sqrtf(snorm[grp]), 1e-12f);
        sfeat[grp][t] = f * scale;
        __syncthreads();

        bool v3 = (t + 384) < IDS;
        float lg0 = bt[t];
        float lg1 = bt[t + 128];
        float lg2 = bt[t + 256];
        float lg3 = v3 ? bt[t + 384] : -1e30f;
        #pragma unroll 8
        for (int ch = 0; ch < EMB; ch++) {
            float fv = sfeat[grp][ch];
            const float* wr = Wt + (size_t)ch * IDS + t;
            lg0 = fmaf(fv, wr[0],   lg0);
            lg1 = fmaf(fv, wr[128], lg1);
            lg2 = fmaf(fv, wr[256], lg2);
            float w3 = v3 ? wr[384] : 0.f;
            lg3 = fmaf(fv, w3, lg3);
        }

        float m = fmaxf(fmaxf(lg0, lg1), fmaxf(lg2, lg3));
        #pragma unroll
        for (int o = 16; o; o >>= 1) m = fmaxf(m, __shfl_xor_sync(0xffffffffu, m, o));
        if ((t & 31) == 0) wtmp[grp][t >> 5] = m;
        __syncthreads();
        m = fmaxf(fmaxf(wtmp[grp][0], wtmp[grp][1]), fmaxf(wtmp[grp][2], wtmp[grp][3]));
        __syncthreads();

        float e = __expf(lg0 - m) + __expf(lg1 - m) + __expf(lg2 - m)
                + (v3 ? __expf(lg3 - m) : 0.f);
        #pragma unroll
        for (int o = 16; o; o >>= 1) e += __shfl_xor_sync(0xffffffffu, e, o);
        if ((t & 31) == 0) wtmp[grp][t >> 5] = e;
        __syncthreads();
        float tot = wtmp[grp][0] + wtmp[grp][1] + wtmp[grp][2] + wtmp[grp][3];
        float lse = m + __logf(tot);

        int rid = reids[bn];
        int rc  = rid < 0 ? 0 : rid;
        if (t == (rc & 127)) {
            int j = rc >> 7;
            starg[grp] = (j == 0) ? lg0 : (j == 1) ? lg1 : (j == 2) ? lg2 : lg3;
        }
        __syncthreads();
        if (t == 0) {
            float valid = (rid >= 0) ? 1.f : 0.f;
            g_rpart[bn] = make_float2((lse - starg[grp]) * valid, valid);
        }
    }

    // =========================== grid-wide completion ticket ===========================
    if (tid == 0) {
        __threadfence();
        unsigned total = gridDim.x * gridDim.y;
        unsigned tk = atomicAdd(&g_ticket, 1u);
        sdone = (tk == total - 1u) ? 1 : 0;
    }
    __syncthreads();
    if (!sdone) return;

    // =========================== final reduction (last block only) =====================
    if (tid < 3) sacc[tid] = 0.f;
    __syncthreads();
    const int w = tid >> 5, lane = tid & 31;
    for (int img = w; img < B; img += 8) {
        float c = 0.f, r = 0.f, np = 0.f;
        for (int i = lane; i < NBLK; i += 32) {
            float4 p = __ldcg(&g_mpart[img * NBLK + i]);
            c += p.x; r += p.y; np += p.z;
        }
        float2 rp = __ldcg(&g_rpart[img * NBOX + lane]);   // NBOX == 32
        float ce = rp.x, va = rp.y;
        #pragma unroll
        for (int o = 16; o; o >>= 1) {
            c  += __shfl_down_sync(0xffffffffu, c,  o);
            r  += __shfl_down_sync(0xffffffffu, r,  o);
            np += __shfl_down_sync(0xffffffffu, np, o);
            ce += __shfl_down_sync(0xffffffffu, ce, o);
            va += __shfl_down_sync(0xffffffffu, va, o);
        }
        if (lane == 0) {
            atomicAdd(&sacc[0], c / fmaxf(np, 1.f));
            atomicAdd(&sacc[1], r / fmaxf(np * 4.f, 1.f));
            atomicAdd(&sacc[2], (np > 0.f) ? ce / fmaxf(va, 1.f) : 0.f);
        }
    }
    __syncthreads();
    if (tid == 0) {
        float inv = 1.f / (float)B;
        out[0] = sacc[0] * inv;
        out[1] = sacc[1] * inv * 50.f;
        out[2] = sacc[2] * inv;
        g_ticket = 0;               // reset for next replay
    }
}

extern "C" void kernel_launch(void* const* d_in, const int* in_sizes, int n_in,
                              void* d_out, int out_size)
{
    const float* cls     = (const float*)d_in[0];   // [B,A,80]
    const float* reg     = (const float*)d_in[1];   // [B,A,4]
    const float* anchors = (const float*)d_in[2];   // [1,A,4]
    const float* emb     = (const float*)d_in[3];   // [B,128,96,96]
    const float* boxes   = (const float*)d_in[4];   // [B,32,4]
    const int*   labels  = (const int*)d_in[5];     // [B,32]
    const int*   reids   = (const int*)d_in[6];     // [B,32]
    const float* Wt      = (const float*)d_in[7];   // [128,500]
    const float* bt      = (const float*)d_in[8];   // [500]
    const float* es      = (const float*)d_in[9];   // scalar

    int B = in_sizes[0] / (A_TOT * NCLS);
    if (B < 1) B = 1;
    if (B > MAXB) B = MAXB;

    fused_kernel<<<dim3(NBLK + RBLK, B), TPB>>>(
        cls, reg, anchors, boxes, labels, emb, reids, Wt, bt, es,
        (float*)d_out, B);
}